// round 3
// baseline (speedup 1.0000x reference)
#include <cuda_runtime.h>
#include <cuda_bf16.h>

#define NMAX 100000
#define EMAX 1200000
#define CSRMAX (NMAX + EMAX)

// ---------------- scratch (device globals; no allocations allowed) ----------
__device__ float  g_h0[NMAX * 64];     // proj output / residual, later reused as h2
__device__ float  g_h1[NMAX * 64];     // layer1 output
__device__ float  g_tmp[NMAX * 64];    // W-transformed features (gather table)
__device__ float  g_byp[NMAX * 3];     // bypass projection
__device__ float  g_dinv[NMAX];
__device__ int    g_deg[NMAX];
__device__ int    g_rowptr[NMAX + 1];
__device__ int    g_cursor[NMAX];
__device__ float2 g_csr[CSRMAX];       // .x = src index (bit-cast), .y = dinv[src]
__device__ int    g_bsum[256];

// ---------------- CSR build --------------------------------------------------
__global__ void deg_init_kernel(int* deg, int N) {
    int i = blockIdx.x * blockDim.x + threadIdx.x;
    if (i < N) deg[i] = 1;  // self-loop
}

__global__ void hist_kernel(const int* __restrict__ col, int* deg, int E) {
    int e = blockIdx.x * blockDim.x + threadIdx.x;
    if (e < E) atomicAdd(&deg[col[e]], 1);
}

__global__ void scan1_kernel(const int* __restrict__ deg, int* rowptr, int* bsum, int N) {
    __shared__ int sm[1024];
    int tid = threadIdx.x;
    int i = blockIdx.x * 1024 + tid;
    int v = (i < N) ? deg[i] : 0;
    sm[tid] = v;
    __syncthreads();
    for (int off = 1; off < 1024; off <<= 1) {
        int t = (tid >= off) ? sm[tid - off] : 0;
        __syncthreads();
        sm[tid] += t;
        __syncthreads();
    }
    int incl = sm[tid];
    if (i < N) rowptr[i] = incl - v;  // exclusive within block
    if (tid == 1023) bsum[blockIdx.x] = incl;
}

__global__ void scan2_kernel(int* bsum, int nb) {
    if (threadIdx.x == 0 && blockIdx.x == 0) {
        int run = 0;
        for (int b = 0; b < nb; ++b) { int t = bsum[b]; bsum[b] = run; run += t; }
    }
}

__global__ void scan3_kernel(const int* __restrict__ deg, int* rowptr,
                             const int* __restrict__ bsum, int* cursor,
                             float* dinv, float2* csr, int N) {
    int i = blockIdx.x * blockDim.x + threadIdx.x;
    if (i >= N) return;
    int rp = rowptr[i] + bsum[i >> 10];
    rowptr[i] = rp;
    cursor[i] = rp + 1;  // slot rp reserved for self-loop
    float dv = rsqrtf((float)deg[i]);
    dinv[i] = dv;
    csr[rp] = make_float2(__int_as_float(i), dv);
    if (i == N - 1) rowptr[N] = rp + deg[i];
}

__global__ void fill_kernel(const int* __restrict__ row, const int* __restrict__ col,
                            const float* __restrict__ dinv, int* cursor,
                            float2* csr, int E) {
    int e = blockIdx.x * blockDim.x + threadIdx.x;
    if (e >= E) return;
    int d = col[e];
    int pos = atomicAdd(&cursor[d], 1);
    int s = row[e];
    csr[pos] = make_float2(__int_as_float(s), dinv[s]);
}

// ---------------- GEMMs ------------------------------------------------------
// out[n][c] = sum_k A[n][k]*W[c][k]   (64x64 weights, K=64, no bias)
__global__ void __launch_bounds__(128) gemm64_kernel(
    const float* __restrict__ A, const float* __restrict__ W,
    float* __restrict__ out, int N)
{
    __shared__ float Xs[64][65];
    __shared__ float Ws[64][65];
    int tid = threadIdx.x;
    int row0 = blockIdx.x * 64;
    int tr = tid >> 3;   // 0..15
    int tc = tid & 7;    // 0..7

    for (int l = tid; l < 1024; l += 128) {
        int r = l >> 4, k4 = (l & 15) * 4;
        int n = row0 + r;
        float4 xv = make_float4(0.f, 0.f, 0.f, 0.f);
        if (n < N) xv = *(const float4*)(A + n * 64 + k4);
        Xs[r][k4] = xv.x; Xs[r][k4 + 1] = xv.y; Xs[r][k4 + 2] = xv.z; Xs[r][k4 + 3] = xv.w;
        float4 wv = *(const float4*)(W + r * 64 + k4);
        Ws[r][k4] = wv.x; Ws[r][k4 + 1] = wv.y; Ws[r][k4 + 2] = wv.z; Ws[r][k4 + 3] = wv.w;
    }
    __syncthreads();

    float acc[4][8];
#pragma unroll
    for (int i = 0; i < 4; ++i)
#pragma unroll
        for (int j = 0; j < 8; ++j) acc[i][j] = 0.f;

#pragma unroll 4
    for (int k = 0; k < 64; ++k) {
        float a[4], w[8];
#pragma unroll
        for (int i = 0; i < 4; ++i) a[i] = Xs[tr + i * 16][k];
#pragma unroll
        for (int j = 0; j < 8; ++j) w[j] = Ws[tc + j * 8][k];
#pragma unroll
        for (int i = 0; i < 4; ++i)
#pragma unroll
            for (int j = 0; j < 8; ++j) acc[i][j] = fmaf(a[i], w[j], acc[i][j]);
    }

#pragma unroll
    for (int i = 0; i < 4; ++i) {
        int n = row0 + tr + i * 16;
        if (n < N) {
#pragma unroll
            for (int j = 0; j < 8; ++j) out[n * 64 + tc + j * 8] = acc[i][j];
        }
    }
}

// proj (K=128, +bias) fused with bypass (x @ byp_W.T + byp_b, 3 outputs)
__global__ void __launch_bounds__(128) gemm_proj_kernel(
    const float* __restrict__ x, const float* __restrict__ Wp,
    const float* __restrict__ bp, const float* __restrict__ Wb,
    const float* __restrict__ bb, float* __restrict__ h0,
    float* __restrict__ byp, int N)
{
    __shared__ float Xs[64][65];
    __shared__ float Ws[64][65];
    __shared__ float Bs[3][65];
    int tid = threadIdx.x;
    int row0 = blockIdx.x * 64;
    int tr = tid >> 3;
    int tc = tid & 7;

    float acc[4][8];
    float bacc[4] = {0.f, 0.f, 0.f, 0.f};
#pragma unroll
    for (int i = 0; i < 4; ++i)
#pragma unroll
        for (int j = 0; j < 8; ++j) acc[i][j] = 0.f;

    for (int kc = 0; kc < 2; ++kc) {
        int kbase = kc * 64;
        for (int l = tid; l < 1024; l += 128) {
            int r = l >> 4, k4 = (l & 15) * 4;
            int n = row0 + r;
            float4 xv = make_float4(0.f, 0.f, 0.f, 0.f);
            if (n < N) xv = *(const float4*)(x + n * 128 + kbase + k4);
            Xs[r][k4] = xv.x; Xs[r][k4 + 1] = xv.y; Xs[r][k4 + 2] = xv.z; Xs[r][k4 + 3] = xv.w;
            float4 wv = *(const float4*)(Wp + r * 128 + kbase + k4);
            Ws[r][k4] = wv.x; Ws[r][k4 + 1] = wv.y; Ws[r][k4 + 2] = wv.z; Ws[r][k4 + 3] = wv.w;
        }
        for (int l = tid; l < 192; l += 128)
            Bs[l >> 6][l & 63] = Wb[(l >> 6) * 128 + kbase + (l & 63)];
        __syncthreads();

#pragma unroll 4
        for (int k = 0; k < 64; ++k) {
            float a[4], w[8];
#pragma unroll
            for (int i = 0; i < 4; ++i) a[i] = Xs[tr + i * 16][k];
#pragma unroll
            for (int j = 0; j < 8; ++j) w[j] = Ws[tc + j * 8][k];
#pragma unroll
            for (int i = 0; i < 4; ++i)
#pragma unroll
                for (int j = 0; j < 8; ++j) acc[i][j] = fmaf(a[i], w[j], acc[i][j]);
            if (tc < 3) {
                float bw = Bs[tc][k];
#pragma unroll
                for (int i = 0; i < 4; ++i) bacc[i] = fmaf(a[i], bw, bacc[i]);
            }
        }
        __syncthreads();
    }

#pragma unroll
    for (int i = 0; i < 4; ++i) {
        int n = row0 + tr + i * 16;
        if (n < N) {
#pragma unroll
            for (int j = 0; j < 8; ++j) {
                int c = tc + j * 8;
                h0[n * 64 + c] = acc[i][j] + bp[c];
            }
            if (tc < 3) byp[n * 3 + tc] = bacc[i] + bb[tc];
        }
    }
}

// ---------------- aggregation (warp per destination node) -------------------
// mode 0: outh = relu(bn(agg + conv_b)) + resid
// mode 1: head fused -> out (N x 3), no residual
__global__ void __launch_bounds__(256) agg_kernel(
    const float* __restrict__ tmp, const float2* __restrict__ csr,
    const int* __restrict__ rowptr, const float* __restrict__ dinv,
    const float* __restrict__ convb, const float* __restrict__ bng,
    const float* __restrict__ bnb, const float* __restrict__ resid,
    float* __restrict__ outh, const float* __restrict__ headW,
    const float* __restrict__ headb, const float* __restrict__ byp,
    float* __restrict__ out, int N, int mode)
{
    int gt = blockIdx.x * blockDim.x + threadIdx.x;
    int v = gt >> 5;
    int lane = gt & 31;
    if (v >= N) return;

    int s = rowptr[v];
    int e = rowptr[v + 1];
    const float2* hp = (const float2*)tmp;
    float ax = 0.f, ay = 0.f;
    for (int p = s; p < e; ++p) {
        float2 ent = csr[p];                 // warp-uniform broadcast load
        int src = __float_as_int(ent.x);
        float2 h = hp[src * 32 + lane];      // 256B coalesced gather
        ax = fmaf(ent.y, h.x, ax);
        ay = fmaf(ent.y, h.y, ay);
    }
    float dv = dinv[v];
    int c0 = lane * 2;
    const float bninv = rsqrtf(1.0f + 1e-5f);
    float v0 = fmaf(fmaf(ax, dv, convb[c0]),     bng[c0] * bninv,     bnb[c0]);
    float v1 = fmaf(fmaf(ay, dv, convb[c0 + 1]), bng[c0 + 1] * bninv, bnb[c0 + 1]);
    v0 = fmaxf(v0, 0.f);
    v1 = fmaxf(v1, 0.f);

    if (mode == 0) {
        float2 r = ((const float2*)resid)[v * 32 + lane];
        float2 o;
        o.x = v0 + r.x;
        o.y = v1 + r.y;
        ((float2*)outh)[v * 32 + lane] = o;
    } else {
        float p0 = v0 * headW[c0]       + v1 * headW[c0 + 1];
        float p1 = v0 * headW[67 + c0]  + v1 * headW[67 + c0 + 1];
        float p2 = v0 * headW[134 + c0] + v1 * headW[134 + c0 + 1];
#pragma unroll
        for (int o = 16; o > 0; o >>= 1) {
            p0 += __shfl_xor_sync(0xffffffffu, p0, o);
            p1 += __shfl_xor_sync(0xffffffffu, p1, o);
            p2 += __shfl_xor_sync(0xffffffffu, p2, o);
        }
        if (lane == 0) {
            float b0 = byp[v * 3], b1 = byp[v * 3 + 1], b2 = byp[v * 3 + 2];
            p0 += headW[64] * b0 + headW[65] * b1 + headW[66] * b2 + headb[0];
            p1 += headW[67 + 64] * b0 + headW[67 + 65] * b1 + headW[67 + 66] * b2 + headb[1];
            p2 += headW[134 + 64] * b0 + headW[134 + 65] * b1 + headW[134 + 66] * b2 + headb[2];
            float kappa = fminf(fmaxf(p0 * 5.f + 2.5f, 0.2f), 10.f);
            float tau   = fminf(fmaxf(p2 + 0.5f, 0.05f), 2.f);
            out[v * 3]     = kappa;
            out[v * 3 + 1] = p1;
            out[v * 3 + 2] = tau;
        }
    }
}

// ---------------- launch -----------------------------------------------------
extern "C" void kernel_launch(void* const* d_in, const int* in_sizes, int n_in,
                              void* d_out, int out_size) {
    const float* x      = (const float*)d_in[0];
    const int*   ei     = (const int*)d_in[1];
    const float* projW  = (const float*)d_in[2];
    const float* projB  = (const float*)d_in[3];
    const float* conv1W = (const float*)d_in[4];
    const float* conv1B = (const float*)d_in[5];
    const float* bn1g   = (const float*)d_in[6];
    const float* bn1b   = (const float*)d_in[7];
    const float* conv2W = (const float*)d_in[8];
    const float* conv2B = (const float*)d_in[9];
    const float* bn2g   = (const float*)d_in[10];
    const float* bn2b   = (const float*)d_in[11];
    const float* conv3W = (const float*)d_in[12];
    const float* conv3B = (const float*)d_in[13];
    const float* bn3g   = (const float*)d_in[14];
    const float* bn3b   = (const float*)d_in[15];
    const float* bypW   = (const float*)d_in[16];
    const float* bypB   = (const float*)d_in[17];
    const float* headW  = (const float*)d_in[18];
    const float* headB  = (const float*)d_in[19];
    float* out = (float*)d_out;

    int N = in_sizes[0] / 128;
    int E = in_sizes[1] / 2;
    const int* row = ei;
    const int* col = ei + E;

    float *p_h0, *p_h1, *p_tmp, *p_byp, *p_dinv;
    int *p_deg, *p_rowptr, *p_cursor, *p_bsum;
    float2* p_csr;
    cudaGetSymbolAddress((void**)&p_h0, g_h0);
    cudaGetSymbolAddress((void**)&p_h1, g_h1);
    cudaGetSymbolAddress((void**)&p_tmp, g_tmp);
    cudaGetSymbolAddress((void**)&p_byp, g_byp);
    cudaGetSymbolAddress((void**)&p_dinv, g_dinv);
    cudaGetSymbolAddress((void**)&p_deg, g_deg);
    cudaGetSymbolAddress((void**)&p_rowptr, g_rowptr);
    cudaGetSymbolAddress((void**)&p_cursor, g_cursor);
    cudaGetSymbolAddress((void**)&p_bsum, g_bsum);
    cudaGetSymbolAddress((void**)&p_csr, g_csr);

    int nb = (N + 1023) / 1024;

    deg_init_kernel<<<(N + 255) / 256, 256>>>(p_deg, N);
    hist_kernel<<<(E + 255) / 256, 256>>>(col, p_deg, E);
    scan1_kernel<<<nb, 1024>>>(p_deg, p_rowptr, p_bsum, N);
    scan2_kernel<<<1, 32>>>(p_bsum, nb);
    scan3_kernel<<<(N + 255) / 256, 256>>>(p_deg, p_rowptr, p_bsum, p_cursor, p_dinv, p_csr, N);
    fill_kernel<<<(E + 255) / 256, 256>>>(row, col, p_dinv, p_cursor, p_csr, E);

    int gemm_blocks = (N + 63) / 64;
    int agg_blocks = (N * 32 + 255) / 256;

    // h0 = x @ projW.T + projB ; byp = x @ bypW.T + bypB
    gemm_proj_kernel<<<gemm_blocks, 128>>>(x, projW, projB, bypW, bypB, p_h0, p_byp, N);

    // layer 1: h1 = relu(bn(agg(h0 @ W1.T) + b1)) + h0
    gemm64_kernel<<<gemm_blocks, 128>>>(p_h0, conv1W, p_tmp, N);
    agg_kernel<<<agg_blocks, 256>>>(p_tmp, p_csr, p_rowptr, p_dinv,
                                    conv1B, bn1g, bn1b, p_h0, p_h1,
                                    nullptr, nullptr, nullptr, nullptr, N, 0);

    // layer 2: h2 (stored in g_h0) = relu(bn(agg(h1 @ W2.T) + b2)) + h1
    gemm64_kernel<<<gemm_blocks, 128>>>(p_h1, conv2W, p_tmp, N);
    agg_kernel<<<agg_blocks, 256>>>(p_tmp, p_csr, p_rowptr, p_dinv,
                                    conv2B, bn2g, bn2b, p_h1, p_h0,
                                    nullptr, nullptr, nullptr, nullptr, N, 0);

    // layer 3 + head fused -> out
    gemm64_kernel<<<gemm_blocks, 128>>>(p_h0, conv3W, p_tmp, N);
    agg_kernel<<<agg_blocks, 256>>>(p_tmp, p_csr, p_rowptr, p_dinv,
                                    conv3B, bn3g, bn3b, nullptr, nullptr,
                                    headW, headB, p_byp, out, N, 1);
}

// round 4
// speedup vs baseline: 1.0709x; 1.0709x over previous
#include <cuda_runtime.h>
#include <cuda_fp16.h>
#include <cuda_bf16.h>

#define NMAX 100000
#define EMAX 1200000
#define CSRMAX (NMAX + EMAX)

// ---------------- scratch (device globals; no allocations allowed) ----------
__device__ float   g_h0[NMAX * 64];     // proj output / residual, later reused as h2
__device__ float   g_h1[NMAX * 64];     // layer1 output
__device__ __half2 g_tmp[NMAX * 32];    // W-transformed features (fp16 gather table)
__device__ float   g_byp[NMAX * 3];     // bypass projection
__device__ float   g_dinv[NMAX];
__device__ int     g_deg[NMAX];
__device__ int     g_rowptr[NMAX + 1];
__device__ int     g_cursor[NMAX];
__device__ float2  g_csr[CSRMAX];       // .x = src index (bit-cast), .y = dinv[src]
__device__ int     g_bsum[256];

// ---------------- f32x2 helpers (FFMA2) -------------------------------------
__device__ __forceinline__ void ffma2(unsigned long long& d,
                                      unsigned long long a,
                                      unsigned long long b) {
    asm("fma.rn.f32x2 %0, %1, %2, %0;" : "+l"(d) : "l"(a), "l"(b));
}
__device__ __forceinline__ unsigned long long dup2(float x) {
    unsigned long long r;
    unsigned u = __float_as_uint(x);
    asm("mov.b64 %0, {%1, %1};" : "=l"(r) : "r"(u));
    return r;
}
__device__ __forceinline__ float lo32(unsigned long long v) {
    return __uint_as_float((unsigned)(v & 0xffffffffull));
}
__device__ __forceinline__ float hi32(unsigned long long v) {
    return __uint_as_float((unsigned)(v >> 32));
}

// ---------------- CSR build --------------------------------------------------
__global__ void deg_init_kernel(int* deg, int N) {
    int i = blockIdx.x * blockDim.x + threadIdx.x;
    if (i < N) deg[i] = 1;  // self-loop
}

__global__ void hist_kernel(const int* __restrict__ col, int* deg, int E) {
    int e = blockIdx.x * blockDim.x + threadIdx.x;
    if (e < E) atomicAdd(&deg[col[e]], 1);
}

__global__ void scan1_kernel(const int* __restrict__ deg, int* rowptr, int* bsum, int N) {
    __shared__ int sm[1024];
    int tid = threadIdx.x;
    int i = blockIdx.x * 1024 + tid;
    int v = (i < N) ? deg[i] : 0;
    sm[tid] = v;
    __syncthreads();
    for (int off = 1; off < 1024; off <<= 1) {
        int t = (tid >= off) ? sm[tid - off] : 0;
        __syncthreads();
        sm[tid] += t;
        __syncthreads();
    }
    int incl = sm[tid];
    if (i < N) rowptr[i] = incl - v;  // exclusive within block
    if (tid == 1023) bsum[blockIdx.x] = incl;
}

// parallel exclusive scan of block sums (nb <= 128)
__global__ void scan2_kernel(int* bsum, int nb) {
    __shared__ int sm[128];
    int t = threadIdx.x;
    int v = (t < nb) ? bsum[t] : 0;
    sm[t] = v;
    __syncthreads();
    for (int off = 1; off < 128; off <<= 1) {
        int u = (t >= off) ? sm[t - off] : 0;
        __syncthreads();
        sm[t] += u;
        __syncthreads();
    }
    if (t < nb) bsum[t] = sm[t] - v;
}

__global__ void scan3_kernel(const int* __restrict__ deg, int* rowptr,
                             const int* __restrict__ bsum, int* cursor,
                             float* dinv, float2* csr, int N) {
    int i = blockIdx.x * blockDim.x + threadIdx.x;
    if (i >= N) return;
    int rp = rowptr[i] + bsum[i >> 10];
    rowptr[i] = rp;
    cursor[i] = rp + 1;  // slot rp reserved for self-loop
    float dv = rsqrtf((float)deg[i]);
    dinv[i] = dv;
    csr[rp] = make_float2(__int_as_float(i), dv);
    if (i == N - 1) rowptr[N] = rp + deg[i];
}

__global__ void fill_kernel(const int* __restrict__ row, const int* __restrict__ col,
                            const float* __restrict__ dinv, int* cursor,
                            float2* csr, int E) {
    int e = blockIdx.x * blockDim.x + threadIdx.x;
    if (e >= E) return;
    int d = col[e];
    int pos = atomicAdd(&cursor[d], 1);
    int s = row[e];
    csr[pos] = make_float2(__int_as_float(s), dinv[s]);
}

// ---------------- 64x64 GEMM (FFMA2), fp16 output ---------------------------
// out_half2[n][m] covers channels {2m, 2m+1}; out[n][c] = sum_k A[n][k]*W[c][k]
__global__ void __launch_bounds__(128) gemm64h_kernel(
    const float* __restrict__ A, const float* __restrict__ W,
    __half2* __restrict__ out, int N)
{
    __shared__ float Xs[64][65];
    __shared__ float Ws[64][66];   // transposed: Ws[k][c]
    int tid = threadIdx.x;
    int row0 = blockIdx.x * 64;
    int tr  = tid >> 3;            // 0..15
    int tc2 = (tid & 7) * 2;       // even col base 0..14

    for (int l = tid; l < 1024; l += 128) {
        int r = l >> 4, k4 = (l & 15) * 4;
        int n = row0 + r;
        float4 xv = make_float4(0.f, 0.f, 0.f, 0.f);
        if (n < N) xv = *(const float4*)(A + n * 64 + k4);
        Xs[r][k4] = xv.x; Xs[r][k4 + 1] = xv.y; Xs[r][k4 + 2] = xv.z; Xs[r][k4 + 3] = xv.w;
        float4 wv = *(const float4*)(W + r * 64 + k4);
        Ws[k4][r] = wv.x; Ws[k4 + 1][r] = wv.y; Ws[k4 + 2][r] = wv.z; Ws[k4 + 3][r] = wv.w;
    }
    __syncthreads();

    unsigned long long acc[4][4];
#pragma unroll
    for (int i = 0; i < 4; ++i)
#pragma unroll
        for (int j = 0; j < 4; ++j) acc[i][j] = 0ull;

#pragma unroll 4
    for (int k = 0; k < 64; ++k) {
        unsigned long long aa[4], wv[4];
#pragma unroll
        for (int i = 0; i < 4; ++i) aa[i] = dup2(Xs[tr + i * 16][k]);
#pragma unroll
        for (int j = 0; j < 4; ++j)
            wv[j] = *(const unsigned long long*)&Ws[k][tc2 + 16 * j];
#pragma unroll
        for (int i = 0; i < 4; ++i)
#pragma unroll
            for (int j = 0; j < 4; ++j) ffma2(acc[i][j], aa[i], wv[j]);
    }

#pragma unroll
    for (int i = 0; i < 4; ++i) {
        int n = row0 + tr + i * 16;
        if (n < N) {
#pragma unroll
            for (int j = 0; j < 4; ++j) {
                float2 v = make_float2(lo32(acc[i][j]), hi32(acc[i][j]));
                out[n * 32 + (tc2 >> 1) + 8 * j] = __float22half2_rn(v);
            }
        }
    }
}

// ---------------- proj GEMM (K=128, +bias) fused with bypass ----------------
__global__ void __launch_bounds__(128) gemm_proj_kernel(
    const float* __restrict__ x, const float* __restrict__ Wp,
    const float* __restrict__ bp, const float* __restrict__ Wb,
    const float* __restrict__ bb, float* __restrict__ h0,
    float* __restrict__ byp, int N)
{
    __shared__ float Xs[64][65];
    __shared__ float Ws[64][66];   // transposed per chunk: Ws[k][c]
    __shared__ float Bs[3][65];
    int tid = threadIdx.x;
    int row0 = blockIdx.x * 64;
    int tr  = tid >> 3;
    int tc2 = (tid & 7) * 2;

    unsigned long long acc[4][4];
    float bacc[4] = {0.f, 0.f, 0.f, 0.f};
#pragma unroll
    for (int i = 0; i < 4; ++i)
#pragma unroll
        for (int j = 0; j < 4; ++j) acc[i][j] = 0ull;

    for (int kc = 0; kc < 2; ++kc) {
        int kbase = kc * 64;
        for (int l = tid; l < 1024; l += 128) {
            int r = l >> 4, k4 = (l & 15) * 4;
            int n = row0 + r;
            float4 xv = make_float4(0.f, 0.f, 0.f, 0.f);
            if (n < N) xv = *(const float4*)(x + n * 128 + kbase + k4);
            Xs[r][k4] = xv.x; Xs[r][k4 + 1] = xv.y; Xs[r][k4 + 2] = xv.z; Xs[r][k4 + 3] = xv.w;
            float4 wv = *(const float4*)(Wp + r * 128 + kbase + k4);
            Ws[k4][r] = wv.x; Ws[k4 + 1][r] = wv.y; Ws[k4 + 2][r] = wv.z; Ws[k4 + 3][r] = wv.w;
        }
        for (int l = tid; l < 192; l += 128)
            Bs[l >> 6][l & 63] = Wb[(l >> 6) * 128 + kbase + (l & 63)];
        __syncthreads();

        int tc = tid & 7;
#pragma unroll 4
        for (int k = 0; k < 64; ++k) {
            float a_s[4];
            unsigned long long aa[4], wv[4];
#pragma unroll
            for (int i = 0; i < 4; ++i) { a_s[i] = Xs[tr + i * 16][k]; aa[i] = dup2(a_s[i]); }
#pragma unroll
            for (int j = 0; j < 4; ++j)
                wv[j] = *(const unsigned long long*)&Ws[k][tc2 + 16 * j];
#pragma unroll
            for (int i = 0; i < 4; ++i)
#pragma unroll
                for (int j = 0; j < 4; ++j) ffma2(acc[i][j], aa[i], wv[j]);
            if (tc < 3) {
                float bw = Bs[tc][k];
#pragma unroll
                for (int i = 0; i < 4; ++i) bacc[i] = fmaf(a_s[i], bw, bacc[i]);
            }
        }
        __syncthreads();
    }

    int tc = tid & 7;
#pragma unroll
    for (int i = 0; i < 4; ++i) {
        int n = row0 + tr + i * 16;
        if (n < N) {
#pragma unroll
            for (int j = 0; j < 4; ++j) {
                int c = tc2 + 16 * j;
                float2 v;
                v.x = lo32(acc[i][j]) + bp[c];
                v.y = hi32(acc[i][j]) + bp[c + 1];
                *(float2*)(h0 + n * 64 + c) = v;
            }
            if (tc < 3) byp[n * 3 + tc] = bacc[i] + bb[tc];
        }
    }
}

// ---------------- aggregation (warp per destination node) -------------------
// mode 0: outh = relu(bn(agg + conv_b)) + resid
// mode 1: head fused -> out (N x 3), no residual
__global__ void __launch_bounds__(256) agg_kernel(
    const __half2* __restrict__ tmp, const float2* __restrict__ csr,
    const int* __restrict__ rowptr, const float* __restrict__ dinv,
    const float* __restrict__ convb, const float* __restrict__ bng,
    const float* __restrict__ bnb, const float* __restrict__ resid,
    float* __restrict__ outh, const float* __restrict__ headW,
    const float* __restrict__ headb, const float* __restrict__ byp,
    float* __restrict__ out, int N, int mode)
{
    int gt = blockIdx.x * blockDim.x + threadIdx.x;
    int v = gt >> 5;
    int lane = gt & 31;
    if (v >= N) return;

    int s = rowptr[v];
    int e = rowptr[v + 1];
    float ax = 0.f, ay = 0.f;
    int p = s;
    for (; p + 1 < e; p += 2) {
        float2 e0 = csr[p];
        float2 e1 = csr[p + 1];
        int s0 = __float_as_int(e0.x);
        int s1 = __float_as_int(e1.x);
        float2 h0v = __half22float2(tmp[s0 * 32 + lane]);
        float2 h1v = __half22float2(tmp[s1 * 32 + lane]);
        ax = fmaf(e0.y, h0v.x, ax);
        ay = fmaf(e0.y, h0v.y, ay);
        ax = fmaf(e1.y, h1v.x, ax);
        ay = fmaf(e1.y, h1v.y, ay);
    }
    if (p < e) {
        float2 e0 = csr[p];
        int s0 = __float_as_int(e0.x);
        float2 h0v = __half22float2(tmp[s0 * 32 + lane]);
        ax = fmaf(e0.y, h0v.x, ax);
        ay = fmaf(e0.y, h0v.y, ay);
    }

    float dv = dinv[v];
    int c0 = lane * 2;
    const float bninv = rsqrtf(1.0f + 1e-5f);
    float v0 = fmaf(fmaf(ax, dv, convb[c0]),     bng[c0] * bninv,     bnb[c0]);
    float v1 = fmaf(fmaf(ay, dv, convb[c0 + 1]), bng[c0 + 1] * bninv, bnb[c0 + 1]);
    v0 = fmaxf(v0, 0.f);
    v1 = fmaxf(v1, 0.f);

    if (mode == 0) {
        float2 r = ((const float2*)resid)[v * 32 + lane];
        float2 o;
        o.x = v0 + r.x;
        o.y = v1 + r.y;
        ((float2*)outh)[v * 32 + lane] = o;
    } else {
        float p0 = v0 * headW[c0]       + v1 * headW[c0 + 1];
        float p1 = v0 * headW[67 + c0]  + v1 * headW[67 + c0 + 1];
        float p2 = v0 * headW[134 + c0] + v1 * headW[134 + c0 + 1];
#pragma unroll
        for (int o = 16; o > 0; o >>= 1) {
            p0 += __shfl_xor_sync(0xffffffffu, p0, o);
            p1 += __shfl_xor_sync(0xffffffffu, p1, o);
            p2 += __shfl_xor_sync(0xffffffffu, p2, o);
        }
        if (lane == 0) {
            float b0 = byp[v * 3], b1 = byp[v * 3 + 1], b2 = byp[v * 3 + 2];
            p0 += headW[64] * b0 + headW[65] * b1 + headW[66] * b2 + headb[0];
            p1 += headW[67 + 64] * b0 + headW[67 + 65] * b1 + headW[67 + 66] * b2 + headb[1];
            p2 += headW[134 + 64] * b0 + headW[134 + 65] * b1 + headW[134 + 66] * b2 + headb[2];
            float kappa = fminf(fmaxf(p0 * 5.f + 2.5f, 0.2f), 10.f);
            float tau   = fminf(fmaxf(p2 + 0.5f, 0.05f), 2.f);
            out[v * 3]     = kappa;
            out[v * 3 + 1] = p1;
            out[v * 3 + 2] = tau;
        }
    }
}

// ---------------- launch -----------------------------------------------------
extern "C" void kernel_launch(void* const* d_in, const int* in_sizes, int n_in,
                              void* d_out, int out_size) {
    const float* x      = (const float*)d_in[0];
    const int*   ei     = (const int*)d_in[1];
    const float* projW  = (const float*)d_in[2];
    const float* projB  = (const float*)d_in[3];
    const float* conv1W = (const float*)d_in[4];
    const float* conv1B = (const float*)d_in[5];
    const float* bn1g   = (const float*)d_in[6];
    const float* bn1b   = (const float*)d_in[7];
    const float* conv2W = (const float*)d_in[8];
    const float* conv2B = (const float*)d_in[9];
    const float* bn2g   = (const float*)d_in[10];
    const float* bn2b   = (const float*)d_in[11];
    const float* conv3W = (const float*)d_in[12];
    const float* conv3B = (const float*)d_in[13];
    const float* bn3g   = (const float*)d_in[14];
    const float* bn3b   = (const float*)d_in[15];
    const float* bypW   = (const float*)d_in[16];
    const float* bypB   = (const float*)d_in[17];
    const float* headW  = (const float*)d_in[18];
    const float* headB  = (const float*)d_in[19];
    float* out = (float*)d_out;

    int N = in_sizes[0] / 128;
    int E = in_sizes[1] / 2;
    const int* row = ei;
    const int* col = ei + E;

    float *p_h0, *p_h1, *p_byp, *p_dinv;
    __half2* p_tmp;
    int *p_deg, *p_rowptr, *p_cursor, *p_bsum;
    float2* p_csr;
    cudaGetSymbolAddress((void**)&p_h0, g_h0);
    cudaGetSymbolAddress((void**)&p_h1, g_h1);
    cudaGetSymbolAddress((void**)&p_tmp, g_tmp);
    cudaGetSymbolAddress((void**)&p_byp, g_byp);
    cudaGetSymbolAddress((void**)&p_dinv, g_dinv);
    cudaGetSymbolAddress((void**)&p_deg, g_deg);
    cudaGetSymbolAddress((void**)&p_rowptr, g_rowptr);
    cudaGetSymbolAddress((void**)&p_cursor, g_cursor);
    cudaGetSymbolAddress((void**)&p_bsum, g_bsum);
    cudaGetSymbolAddress((void**)&p_csr, g_csr);

    int nb = (N + 1023) / 1024;

    deg_init_kernel<<<(N + 255) / 256, 256>>>(p_deg, N);
    hist_kernel<<<(E + 255) / 256, 256>>>(col, p_deg, E);
    scan1_kernel<<<nb, 1024>>>(p_deg, p_rowptr, p_bsum, N);
    scan2_kernel<<<1, 128>>>(p_bsum, nb);
    scan3_kernel<<<(N + 255) / 256, 256>>>(p_deg, p_rowptr, p_bsum, p_cursor, p_dinv, p_csr, N);
    fill_kernel<<<(E + 255) / 256, 256>>>(row, col, p_dinv, p_cursor, p_csr, E);

    int gemm_blocks = (N + 63) / 64;
    int agg_blocks = (N * 32 + 255) / 256;

    // h0 = x @ projW.T + projB ; byp = x @ bypW.T + bypB
    gemm_proj_kernel<<<gemm_blocks, 128>>>(x, projW, projB, bypW, bypB, p_h0, p_byp, N);

    // layer 1: h1 = relu(bn(agg(h0 @ W1.T) + b1)) + h0
    gemm64h_kernel<<<gemm_blocks, 128>>>(p_h0, conv1W, p_tmp, N);
    agg_kernel<<<agg_blocks, 256>>>(p_tmp, p_csr, p_rowptr, p_dinv,
                                    conv1B, bn1g, bn1b, p_h0, p_h1,
                                    nullptr, nullptr, nullptr, nullptr, N, 0);

    // layer 2: h2 (stored in g_h0) = relu(bn(agg(h1 @ W2.T) + b2)) + h1
    gemm64h_kernel<<<gemm_blocks, 128>>>(p_h1, conv2W, p_tmp, N);
    agg_kernel<<<agg_blocks, 256>>>(p_tmp, p_csr, p_rowptr, p_dinv,
                                    conv2B, bn2g, bn2b, p_h1, p_h0,
                                    nullptr, nullptr, nullptr, nullptr, N, 0);

    // layer 3 + head fused -> out
    gemm64h_kernel<<<gemm_blocks, 128>>>(p_h0, conv3W, p_tmp, N);
    agg_kernel<<<agg_blocks, 256>>>(p_tmp, p_csr, p_rowptr, p_dinv,
                                    conv3B, bn3g, bn3b, nullptr, nullptr,
                                    headW, headB, p_byp, out, N, 1);
}